// round 17
// baseline (speedup 1.0000x reference)
#include <cuda_runtime.h>
#include <cuda_bf16.h>
#include <cstdint>
#include <cstddef>

// ---------------- problem constants ----------------
constexpr int N_  = 16;
constexpr int D_  = 16;
constexpr int S_  = 112;
constexpr int SS_ = S_ * S_;          // 12544
constexpr int M_  = 2;
constexpr int V_  = 7829;
constexpr int K_  = 512;
constexpr int NM_ = N_ * M_;          // 32
constexpr int NCH = 37;               // v-chunks: 32*37 = 1184 blocks = 8 full waves
constexpr int VCH = 212;              // 37*212 = 7844 >= V_
constexpr int CAP = 24;               // candidate slots per (k, chunk)
constexpr int VT  = 128;              // smem v-tile
constexpr int CYB = 16;               // k_cyc grid.y
constexpr float ZS     = 28.853900817779268f;  // 20 * log2(e): z = ZS * sim
constexpr float SHZ    = 86.561702453337804f;  // 60 * log2(e): fixed shift (cancels)
constexpr float ZMARG  = 18.755035531556524f;  // 13 * log2(e): keep z > zmax - ZMARG

// ---------------- static device scratch ----------------
__device__ __nv_bfloat16 g_bt[(size_t)NM_ * V_ * K_];   // [nm][v][k] e-tilde (unnormalized)
__device__ float g_rcs[(size_t)NM_ * V_];               // 1 / column sum
__device__ float g_sampled[N_ * K_ * D_];
__device__ float g_fx[N_ * K_], g_fy[N_ * K_];
__device__ float g_rpmax[NM_ * NCH * K_];               // chunk max (z units)
__device__ float g_rpsum[NM_ * NCH * K_];               // chunk sigma (2^(z-zm) sums)
__device__ float g_rk[NM_ * K_];                        // 1/rsum[k]
__device__ int   g_cnt[NM_ * NCH * K_];
__device__ uint2 g_cand[(size_t)NM_ * NCH * K_ * CAP];  // {v, z} then {v, a}
__device__ float g_partial[NM_ * CYB];
__device__ int   g_is64;

static __device__ __forceinline__ float ex2(float x) {
    float r;
    asm("ex2.approx.ftz.f32 %0, %1;" : "=f"(r) : "f"(x));
    return r;
}

// 16-term dot: pre-scaled sampled row (regs) x mesh row (4 float4 from smem)
static __device__ __forceinline__ float dot16s(const float* sk, const float4* mv) {
    float4 m0 = mv[0], m1 = mv[1], m2 = mv[2], m3 = mv[3];
    float s0 =          sk[0]  * m0.x;   s0 = fmaf(sk[1],  m0.y, s0);
    float s1 =          sk[2]  * m0.z;   s1 = fmaf(sk[3],  m0.w, s1);
    float s2 =          sk[4]  * m1.x;   s2 = fmaf(sk[5],  m1.y, s2);
    float s3 =          sk[6]  * m1.z;   s3 = fmaf(sk[7],  m1.w, s3);
    s0 = fmaf(sk[8],  m2.x, s0);  s1 = fmaf(sk[9],  m2.y, s1);
    s2 = fmaf(sk[10], m2.z, s2);  s3 = fmaf(sk[11], m2.w, s3);
    s0 = fmaf(sk[12], m3.x, s0);  s1 = fmaf(sk[13], m3.y, s1);
    s2 = fmaf(sk[14], m3.z, s2);  s3 = fmaf(sk[15], m3.w, s3);
    return (s0 + s1) + (s2 + s3);
}

// ---------------- K0: detect int64 vs int32 indices ----------------
__global__ void k_detect(const int* __restrict__ w) {
    __shared__ int s_allzero;
    if (threadIdx.x == 0) s_allzero = 1;
    __syncthreads();
    int nz = 0;
    for (int i = threadIdx.x * 2 + 1; i < N_ * K_; i += blockDim.x * 2)
        if (w[i] != 0) nz = 1;
    if (nz) atomicAnd(&s_allzero, 0);
    __syncthreads();
    if (threadIdx.x == 0) g_is64 = s_allzero;
}

// ---------------- K1: gather + normalize (pre-scaled by ZS) ----------------
__global__ void k_sample(const float* __restrict__ pix, const void* __restrict__ idxraw) {
    int t = blockIdx.x * blockDim.x + threadIdx.x;
    if (t >= N_ * K_) return;
    long long idx;
    if (g_is64) idx = ((const long long*)idxraw)[t];
    else        idx = (long long)((const int*)idxraw)[t];
    int n = t / K_;
    int p = (int)idx;
    g_fx[t] = (float)(p / S_);
    g_fy[t] = (float)(p % S_);
    const float* base = pix + (size_t)n * D_ * SS_ + p;
    float v[16]; float ss = 0.f;
#pragma unroll
    for (int d = 0; d < 16; d++) { v[d] = base[(size_t)d * SS_]; ss = fmaf(v[d], v[d], ss); }
    float inv = ZS / fmaxf(sqrtf(ss), 1e-6f);      // fold 20*log2(e) into the vector
#pragma unroll
    for (int d = 0; d < 16; d++) g_sampled[t * 16 + d] = v[d] * inv;
}

// ---------------- K1b: filler (keeps k_pass1 in the ncu capture slot) ----------------
__global__ void k_prep() {
    int t = blockIdx.x * blockDim.x + threadIdx.x;
    if (t < NM_ * CYB) g_partial[t] = 0.f;
}

// ---------------- K2: single dense pass (z-domain) ----------------
__global__ void __launch_bounds__(512) k_pass1(const float* __restrict__ mesh) {
    __shared__ float4 smesh[VT * 4];      // 8 KB
    int nm = blockIdx.x, ch = blockIdx.y;
    int k  = threadIdx.x;
    int n = nm / M_, m_ = nm % M_;
    float sk[16];
    const float* sp = &g_sampled[(n * K_ + k) * 16];
#pragma unroll
    for (int d = 0; d < 16; d++) sk[d] = sp[d];
    int v0 = ch * VCH;
    int v1 = min(v0 + VCH, V_);
    const float4* mb = (const float4*)(mesh + (size_t)m_ * V_ * D_);
    __nv_bfloat16* bptr = g_bt + (size_t)nm * V_ * K_ + (size_t)v0 * K_ + k;
    int cbase = (nm * NCH + ch) * K_ + k;
    uint2* cl = g_cand + (size_t)cbase * CAP;

    float zm = -1e30f, sigma = 0.f, thr = -1e30f;
    int cnt = 0;

    for (int tb = v0; tb < v1; tb += VT) {
        int nv = min(VT, v1 - tb);
        for (int i = k; i < nv * 4; i += 512) smesh[i] = mb[(size_t)tb * 4 + i];
        __syncthreads();
#pragma unroll 4
        for (int iv = 0; iv < nv; iv++) {
            float z = dot16s(sk, &smesh[iv * 4]);
            *bptr = __float2bfloat16(ex2(z - SHZ));
            bptr += K_;
            if (z > thr) {
                if (z > zm) { sigma = fmaf(sigma, ex2(zm - z), 1.0f); zm = z; thr = z - ZMARG; }
                else sigma += ex2(z - zm);
                if (cnt >= CAP) {               // rare: compact in place
                    int j = 0;
                    for (int i2 = 0; i2 < cnt; i2++) {
                        uint2 e = cl[i2];
                        if (__uint_as_float(e.y) > thr) cl[j++] = e;
                    }
                    cnt = j;
                }
                if (cnt < CAP) { cl[cnt] = make_uint2((unsigned)(tb + iv), __float_as_uint(z)); cnt++; }
            }
        }
        __syncthreads();
    }
    g_rpmax[cbase] = zm;
    g_rpsum[cbase] = sigma;
    g_cnt[cbase] = cnt;
}

// ---------------- K3: combine chunks -> rk; finalize candidate lists ----------------
__global__ void k_comb() {
    int t = blockIdx.x * blockDim.x + threadIdx.x;
    if (t >= NM_ * K_) return;
    int nm = t / K_, k = t % K_;
    float zstar = -1e30f;
#pragma unroll 1
    for (int c = 0; c < NCH; c++)
        zstar = fmaxf(zstar, g_rpmax[(nm * NCH + c) * K_ + k]);
    float sig = 0.f;
#pragma unroll 1
    for (int c = 0; c < NCH; c++) {
        int b = (nm * NCH + c) * K_ + k;
        sig += g_rpsum[b] * ex2(g_rpmax[b] - zstar);
    }
    g_rk[t] = 1.0f / sig;
    float thr = zstar - ZMARG;
#pragma unroll 1
    for (int c = 0; c < NCH; c++) {
        int b = (nm * NCH + c) * K_ + k;
        int cn = g_cnt[b];
        uint2* cl = g_cand + (size_t)b * CAP;
        int out = 0;
        for (int i = 0; i < cn; i++) {
            uint2 e = cl[i];
            float z = __uint_as_float(e.y);
            if (z > thr)
                cl[out++] = make_uint2(e.x, __float_as_uint(ex2(z - zstar)));
        }
        g_cnt[b] = out;
    }
}

// ---------------- K4: column sums (read-only) -> 1/csum ----------------
__global__ void __launch_bounds__(256) k_csum() {
    int nm = blockIdx.x;
    int v  = blockIdx.y * 8 + (threadIdx.x >> 5);
    int lane = threadIdx.x & 31;
    if (v >= V_) return;
    const uint4* row = (const uint4*)(g_bt + ((size_t)nm * V_ + v) * K_);
    uint4 a = __ldg(&row[lane]);
    uint4 b = __ldg(&row[lane + 32]);
    uint32_t w[8] = {a.x, a.y, a.z, a.w, b.x, b.y, b.z, b.w};
    float s = 0.f;
#pragma unroll
    for (int i = 0; i < 8; i++) {
        float2 f = __bfloat1622float2(*reinterpret_cast<__nv_bfloat162*>(&w[i]));
        s += f.x + f.y;
    }
#pragma unroll
    for (int o = 16; o > 0; o >>= 1) s += __shfl_xor_sync(0xffffffffu, s, o);
    if (lane == 0) g_rcs[(size_t)nm * V_ + v] = __fdividef(1.0f, s);
}

// ---------------- K5: sparse cycle (normalization folded in) ----------------
__global__ void __launch_bounds__(256) k_cyc() {
    __shared__ float sfx[K_], sfy[K_];
    __shared__ float red[256];
    int nm = blockIdx.x, by = blockIdx.y;
    int n = nm / M_;
    int tid = threadIdx.x, w = tid >> 5, lane = tid & 31;
    for (int i = tid; i < K_; i += 256) {
        sfx[i] = g_fx[n * K_ + i];
        sfy[i] = g_fy[n * K_ + i];
    }
    __syncthreads();

    float part = 0.f;
#pragma unroll 1
    for (int i = 0; i < 4; i++) {
        int k = by * 32 + w * 4 + i;
        float rkk = g_rk[nm * K_ + k];
        float acc[16];
#pragma unroll
        for (int j = 0; j < 16; j++) acc[j] = 0.f;

#pragma unroll 1
        for (int ch = 0; ch < NCH; ch++) {
            int base = (nm * NCH + ch) * K_ + k;
            int cnt = g_cnt[base];
            const uint2* cl = g_cand + (size_t)base * CAP;
            if (cnt == 0) continue;
            uint2 ce = cl[0];
            for (int c = 0; c < cnt; c++) {
                uint2 ce_next = (c + 1 < cnt) ? cl[c + 1] : ce;   // prefetch
                float rc = __ldg(&g_rcs[(size_t)nm * V_ + ce.x]);
                float wv = __uint_as_float(ce.y) * rkk * rc;      // A[k,v] * 1/csum
                const uint32_t* row =
                    (const uint32_t*)(g_bt + ((size_t)nm * V_ + ce.x) * K_);
                uint32_t rw[8];
#pragma unroll
                for (int j = 0; j < 8; j++) rw[j] = __ldg(&row[j * 32 + lane]);
#pragma unroll
                for (int j = 0; j < 8; j++) {
                    float2 f = __bfloat1622float2(*reinterpret_cast<__nv_bfloat162*>(&rw[j]));
                    acc[2 * j]     = fmaf(wv, f.x, acc[2 * j]);
                    acc[2 * j + 1] = fmaf(wv, f.y, acc[2 * j + 1]);
                }
                ce = ce_next;
            }
        }

        float xk = sfx[k], yk = sfy[k];
#pragma unroll
        for (int j = 0; j < 8; j++) {
            int q0 = 2 * (j * 32 + lane);
            float dx0 = xk - sfx[q0], dy0 = yk - sfy[q0];
            float dist0 = fmaf(dx0, dx0, dy0 * dy0);
            float wt0 = dist0 * acc[2 * j];
            part = fmaf(wt0, wt0, part);
            float dx1 = xk - sfx[q0 + 1], dy1 = yk - sfy[q0 + 1];
            float dist1 = fmaf(dx1, dx1, dy1 * dy1);
            float wt1 = dist1 * acc[2 * j + 1];
            part = fmaf(wt1, wt1, part);
        }
    }
    red[tid] = part;
    __syncthreads();
    for (int o = 128; o > 0; o >>= 1) {
        if (tid < o) red[tid] += red[tid + o];
        __syncthreads();
    }
    if (tid == 0) g_partial[nm * CYB + by] = red[0];
}

// ---------------- K6: final sqrt + mean ----------------
__global__ void k_final(float* __restrict__ out) {
    int t = threadIdx.x;           // 32 threads, one per nm
    float s = 0.f;
#pragma unroll
    for (int pr = 0; pr < CYB; pr++) s += g_partial[t * CYB + pr];
    float l = sqrtf(s);
#pragma unroll
    for (int o = 16; o > 0; o >>= 1) l += __shfl_xor_sync(0xffffffffu, l, o);
    if (t == 0) out[0] = l / (float)NM_;
}

// ---------------- launch ----------------
extern "C" void kernel_launch(void* const* d_in, const int* in_sizes, int n_in,
                              void* d_out, int out_size) {
    const float* pix  = (const float*)d_in[0];
    const float* mesh = (const float*)d_in[1];
    const void*  idx  = d_in[2];
    float* out = (float*)d_out;
    (void)in_sizes; (void)n_in; (void)out_size;

    k_detect<<<1, 256>>>((const int*)idx);
    k_sample<<<(N_ * K_ + 255) / 256, 256>>>(pix, idx);
    k_prep<<<2, 256>>>();
    k_pass1<<<dim3(NM_, NCH), 512>>>(mesh);    // 1184 blocks = 8 full waves
    k_comb<<<(NM_ * K_ + 255) / 256, 256>>>();
    k_csum<<<dim3(NM_, (V_ + 7) / 8), 256>>>();
    k_cyc<<<dim3(NM_, CYB), 256>>>();
    k_final<<<1, 32>>>(out);
}